// round 15
// baseline (speedup 1.0000x reference)
#include <cuda_runtime.h>

// InfoEnlargeEmbedding: out[b,l,:] = concat(x[b,l,:], x[b,idxs[b,0],:], x[b,idxs[b,1],:])
// B=64, L=1024, D=256, K=2.
// FINAL (R12 shape — best measured end-to-end: 45.47us dur / 40.32us kernel).
// Workload is bound by the part's ~5.2TB/s write-drain rate on the compulsory
// 201MB output stream (floor ~38.7us); this achieves ~96% of it. Ten
// structural variants (MLP depth, warp balance, TMA bulk, persistent, 256-bit,
// .cs/.wt hints, split kernels, L2 bypass) all confirmed the same ceiling.
//
// Structure: single launch, block-specialized, interleaved (g,g,c):
//   - 2048 copy blocks: 8-way unrolled linear memcpy (proven 7.3TB/s body).
//   - 4096 gather blocks: 16-row tiles, 1 L2-hit load -> 8 broadcast stores.
// Each block is internally homogeneous, so retirement never waits on a mixed
// latency class.

static constexpr int B = 64;
static constexpr int L = 1024;
static constexpr int D4 = 64;               // float4 per source row
static constexpr int K = 2;
static constexpr int OUT4 = D4 * (1 + K);   // 192 float4 per output row
static constexpr int T = 256;

// copy section
static constexpr int CP_U = 8;
static constexpr int CP_BLOCKS = (B * L * D4) / (T * CP_U);  // 2048

// gather section
static constexpr int G_ROWS = 16;                            // rows per gather block
static constexpr int G_BLOCKS = (B * L) / G_ROWS;            // 4096
static constexpr int GRT = G_ROWS / 2;                       // 8 stores per thread

static constexpr int GRID = CP_BLOCKS + G_BLOCKS;            // 6144

__global__ void __launch_bounds__(T)
info_enlarge_kernel(const float4* __restrict__ x,
                    const int* __restrict__ idxs,
                    float4* __restrict__ out) {
    const int i = blockIdx.x;
    const int tri = i / 3, rem = i - tri * 3;
    const int t = threadIdx.x;

    if (rem < 2) {
        // ---- gather block: tile of 16 rows, broadcast writes ----
        const int tile = tri * 2 + rem;         // 0..4095
        const int row0 = tile * G_ROWS;         // same b across tile
        const int b    = row0 >> 10;
        const int g    = t & 127;               // gather column 0..127
        const int h    = t >> 7;                // row half
        const int k    = g >> 6;
        const int dd   = g & (D4 - 1);
        const int li   = __ldg(idxs + b * K + k);
        const float4 v = __ldg(x + ((size_t)b * L + li) * D4 + dd);

        float4* o = out + (size_t)(row0 + h * GRT) * OUT4 + D4 + g;
        #pragma unroll
        for (int u = 0; u < GRT; u++)
            o[(size_t)u * OUT4] = v;
    } else {
        // ---- copy block: linear 8-way unrolled strided memcpy ----
        const int ci   = tri;                   // 0..2047
        const int base = ci * (T * CP_U) + t;
        float4 v[CP_U];
        #pragma unroll
        for (int u = 0; u < CP_U; u++)
            v[u] = x[base + u * T];
        #pragma unroll
        for (int u = 0; u < CP_U; u++) {
            const int idx = base + u * T;
            const int bl = idx >> 6, c = idx & (D4 - 1);
            out[(size_t)bl * OUT4 + c] = v[u];
        }
    }
}

extern "C" void kernel_launch(void* const* d_in, const int* in_sizes, int n_in,
                              void* d_out, int out_size) {
    const float4* x  = (const float4*)d_in[0];
    const int* idxs  = (const int*)d_in[1];
    float4* out      = (float4*)d_out;

    info_enlarge_kernel<<<GRID, T>>>(x, idxs, out);
}

// round 16
// speedup vs baseline: 1.0367x; 1.0367x over previous
#include <cuda_runtime.h>

// InfoEnlargeEmbedding: out[b,l,:] = concat(x[b,l,:], x[b,idxs[b,0],:], x[b,idxs[b,1],:])
// B=64, L=1024, D=256, K=2.
//
// FINAL — R6 shape. Best repeated measurements: 45.57/45.70us dur
// (40.16/41.06us kernel), the best mean across all 11 structural variants
// tested (per-warp MLP, warp balance, TMA bulk store, persistent single-wave,
// 256-bit accesses, .cs/.wt cache policies, split kernels, block
// specialization, L2-bypass gather). All variants converge at 40.2-41.9us:
// the workload is bound by the part's ~5.0-5.2 TB/s write-drain rate on the
// compulsory 201MB output stream (floor ~38.7us; this is ~96% of it), with x
// L2-resident so DRAM traffic is essentially the write stream alone.
//
// Structure:
//   - 192 threads/block, 8 output rows per block (all rows share batch b).
//   - Copy lanes (c<64): 8 independent LDG.128 front-batched, then 8 STG.128.
//   - Gather lanes (c>=64): 1 L2-hit LDG.128 broadcast-stored to 8 rows
//     (gather rows identical across l within a batch).
//   - Default cache policy (hints proven neutral).

static constexpr int B = 64;
static constexpr int L = 1024;
static constexpr int D4 = 64;               // float4 per source row
static constexpr int K = 2;
static constexpr int OUT4 = D4 * (1 + K);   // 192 float4 per output row
static constexpr int R = 8;                 // rows (bl) per block

__global__ void __launch_bounds__(OUT4)
info_enlarge_kernel(const float4* __restrict__ x,
                    const int* __restrict__ idxs,
                    float4* __restrict__ out) {
    const int row0 = blockIdx.x * R;        // base bl; all R rows share b
    const int b    = row0 >> 10;            // / L
    const int c    = threadIdx.x;           // 0..191

    if (c < D4) {
        // Straight copy region: 8 independent loads, then 8 stores.
        float4 v[R];
        #pragma unroll
        for (int u = 0; u < R; u++)
            v[u] = x[(size_t)(row0 + u) * D4 + c];
        #pragma unroll
        for (int u = 0; u < R; u++)
            out[(size_t)(row0 + u) * OUT4 + c] = v[u];
    } else {
        // Gather region: same source row for all 8 output rows.
        const int kd = c - D4;
        const int k  = kd >> 6;             // / D4
        const int dd = kd & (D4 - 1);
        const int li = __ldg(idxs + b * K + k);
        const float4 v = __ldg(x + ((size_t)b * L + li) * D4 + dd);
        #pragma unroll
        for (int u = 0; u < R; u++)
            out[(size_t)(row0 + u) * OUT4 + c] = v;
    }
}

extern "C" void kernel_launch(void* const* d_in, const int* in_sizes, int n_in,
                              void* d_out, int out_size) {
    const float4* x  = (const float4*)d_in[0];
    const int* idxs  = (const int*)d_in[1];
    float4* out      = (float4*)d_out;

    info_enlarge_kernel<<<(B * L) / R, OUT4>>>(x, idxs, out);
}